// round 8
// baseline (speedup 1.0000x reference)
#include <cuda_runtime.h>
#include <cuda_bf16.h>
#include <stdint.h>

// x: (B=8, C=3, H=1024, W=1024) fp32; patch=24, stride=16, reflect m=4
// out: (8*64*64, 576, 3) fp32 = 56,623,104 elems (+ maybe (nH,nW)=(64,64)).
#define PATCH_ELEMS 56623104u
#define TOTAL_QUADS 4718592u   // one thread = one quad = 4 px x 3 ch = 12 floats

__device__ __forceinline__ int reflect1024(int v) {
    v = (v < 0) ? -v : v;                 // jnp 'reflect' (no edge repeat)
    v = (v >= 1024) ? (2046 - v) : v;
    return v;
}

__global__ __launch_bounds__(256)
void Patcher_78280073937146_kernel(const float* __restrict__ x,
                                   float* __restrict__ out,
                                   unsigned out_elems) {
    __shared__ float4 sm[8][96];           // per-warp store-transpose buffer (12.3 KB)

    unsigned g = blockIdx.x * 256u + threadIdx.x;
    unsigned lane = threadIdx.x & 31u;
    unsigned w    = threadIdx.x >> 5;

    if (g < TOTAL_QUADS) {
        // ---- decode: patch + pixel-quad ----
        unsigned patch = g / 144u;            // 144 quads per patch
        unsigned u     = g - patch * 144u;    // 0..143
        unsigned iu    = u / 6u;              // patch row 0..23
        unsigned jq    = u - iu * 6u;         // col-quad 0..5

        unsigned b  = patch >> 12;
        unsigned ph = (patch >> 6) & 63u;
        unsigned pw = patch & 63u;

        int y  = reflect1024((int)(ph * 16u + iu) - 4);
        int x0 = (int)(pw * 16u + (jq << 2)) - 4;   // -4 .. 1020 (step 4), or 1024

        unsigned base = ((b * 3u) << 20) + (((unsigned)y) << 10);

        float4 r0, r1, r2;                    // 3 channel planes, pixels p0..p3
        if ((unsigned)x0 <= 1020u) {
            const float* p = x + base + (unsigned)x0;
            r0 = *reinterpret_cast<const float4*>(p);
            r1 = *reinterpret_cast<const float4*>(p + (1u << 20));
            r2 = *reinterpret_cast<const float4*>(p + (2u << 20));
        } else {
            // rare reflected edge (x0 == -4 or 1024): scalar gather
            float t0[4], t1[4], t2[4];
            #pragma unroll
            for (int k = 0; k < 4; ++k) {
                unsigned a = base + (unsigned)reflect1024(x0 + k);
                t0[k] = x[a];
                t1[k] = x[a + (1u << 20)];
                t2[k] = x[a + (2u << 20)];
            }
            r0 = make_float4(t0[0], t0[1], t0[2], t0[3]);
            r1 = make_float4(t1[0], t1[1], t1[2], t1[3]);
            r2 = make_float4(t2[0], t2[1], t2[2], t2[3]);
        }

        // ---- permute channel-major -> (pixel, channel) interleaved ----
        sm[w][3u * lane + 0u] = make_float4(r0.x, r1.x, r2.x, r0.y);
        sm[w][3u * lane + 1u] = make_float4(r1.y, r2.y, r0.z, r1.z);
        sm[w][3u * lane + 2u] = make_float4(r2.z, r0.w, r1.w, r2.w);
        __syncwarp();

        // ---- coalesced stores: each STG.128 = 512B contiguous, 128B-aligned ----
        unsigned warpQuadBase = g - lane;     // multiple of 32
        float4* ov = reinterpret_cast<float4*>(out)
                   + (size_t)warpQuadBase * 3u + lane;
        __stcs(ov +  0, sm[w][lane +  0u]);
        __stcs(ov + 32, sm[w][lane + 32u]);
        __stcs(ov + 64, sm[w][lane + 64u]);
    } else {
        // trailing (nH, nW) = (64, 64) slots, if the harness appends them
        unsigned e = PATCH_ELEMS + (g - TOTAL_QUADS);
        if (e < out_elems) out[e] = 64.0f;
    }
}

extern "C" void kernel_launch(void* const* d_in, const int* in_sizes, int n_in,
                              void* d_out, int out_size) {
    const float* x = (const float*)d_in[0];
    float* out = (float*)d_out;
    unsigned out_elems = (unsigned)out_size;

    unsigned mainBlocks  = TOTAL_QUADS / 256u;   // 18432 exact
    unsigned extraElems  = (out_elems > PATCH_ELEMS) ? (out_elems - PATCH_ELEMS) : 0u;
    unsigned extraBlocks = (extraElems + 255u) / 256u;
    Patcher_78280073937146_kernel<<<mainBlocks + extraBlocks, 256>>>(x, out, out_elems);
}

// round 9
// speedup vs baseline: 1.2254x; 1.2254x over previous
#include <cuda_runtime.h>
#include <cuda_bf16.h>
#include <stdint.h>

// x: (B=8, C=3, H=1024, W=1024) fp32; patch=24, stride=16, reflect m=4
// out: (8*64*64, 576, 3) fp32 = 56,623,104 elems (+ maybe (nH,nW)=(64,64)).
#define PATCH_ELEMS 56623104u
#define NROWCTAS 12288u        // 8 images x 64 ph x 24 iu
#define THREADS  384u          // one thread per (pw, jq) quad of the row

__device__ __forceinline__ int reflect1024(int v) {
    v = (v < 0) ? -v : v;                 // jnp 'reflect' (no edge repeat)
    v = (v >= 1024) ? (2046 - v) : v;
    return v;
}

__global__ __launch_bounds__(THREADS)
void Patcher_78280073937146_kernel(const float* __restrict__ x,
                                   float* __restrict__ out,
                                   unsigned out_elems) {
    __shared__ float4 smq[1152];          // 18 KB: staged row output

    unsigned bid = blockIdx.x;
    unsigned t   = threadIdx.x;

    if (bid >= NROWCTAS) {
        // trailing (nH, nW) = (64, 64) slots, if the harness appends them
        unsigned e = PATCH_ELEMS + (bid - NROWCTAS) * THREADS + t;
        if (e < out_elems) out[e] = 64.0f;
        return;
    }

    // ---- CTA decode: one (b, ph, iu) output row ----
    unsigned b   = bid / 1536u;           // image 0..7
    unsigned rem = bid - b * 1536u;
    unsigned ph  = rem / 24u;             // patch row 0..63
    unsigned iu  = rem - ph * 24u;        // row within patch 0..23

    int y = reflect1024((int)(ph * 16u + iu) - 4);
    unsigned base = ((b * 3u) << 20) + (((unsigned)y) << 10);

    // ---- per-thread load: quad (pw, jq) from the single image row y ----
    unsigned pw = t / 6u;                 // 0..63
    unsigned jq = t - pw * 6u;            // 0..5
    int x0 = (int)(pw * 16u + (jq << 2)) - 4;   // -4 .. 1024, 16B-aligned

    float4 r0, r1, r2;                    // channel planes c0,c1,c2, pixels 0..3
    if ((unsigned)x0 <= 1020u) {
        const float* p = x + base + (unsigned)x0;
        r0 = *reinterpret_cast<const float4*>(p);
        r1 = *reinterpret_cast<const float4*>(p + (1u << 20));
        r2 = *reinterpret_cast<const float4*>(p + (2u << 20));
    } else {
        // only threads 0 (x0=-4) and 383 (x0=1024): reflected scalar gather
        float t0[4], t1[4], t2[4];
        #pragma unroll
        for (int k = 0; k < 4; ++k) {
            unsigned a = base + (unsigned)reflect1024(x0 + k);
            t0[k] = x[a];
            t1[k] = x[a + (1u << 20)];
            t2[k] = x[a + (2u << 20)];
        }
        r0 = make_float4(t0[0], t0[1], t0[2], t0[3]);
        r1 = make_float4(t1[0], t1[1], t1[2], t1[3]);
        r2 = make_float4(t2[0], t2[1], t2[2], t2[3]);
    }

    // ---- permute channel-major -> (pixel, channel); stage in smem ----
    // quad q = pw*6+jq owns float4 slots q*3+k  (3 coprime 8 -> conflict-free)
    smq[t * 3u + 0u] = make_float4(r0.x, r1.x, r2.x, r0.y);
    smq[t * 3u + 1u] = make_float4(r1.y, r2.y, r0.z, r1.z);
    smq[t * 3u + 2u] = make_float4(r2.z, r0.w, r1.w, r2.w);
    __syncthreads();

    // ---- emit: 64 patches x 18 float4 (288B contiguous per patch) ----
    // global float4 addr for (pw, r): (b*4096 + ph*64 + pw)*432 + iu*18 + r
    unsigned outBase = ((b << 12) + (ph << 6)) * 432u + iu * 18u;
    float4* ov = reinterpret_cast<float4*>(out);
    #pragma unroll
    for (unsigned i = 0; i < 3u; ++i) {
        unsigned f  = t + i * THREADS;    // 0..1151
        unsigned pwS = f / 18u;
        unsigned r   = f - pwS * 18u;
        __stcs(ov + outBase + pwS * 432u + r, smq[f]);
    }
}

extern "C" void kernel_launch(void* const* d_in, const int* in_sizes, int n_in,
                              void* d_out, int out_size) {
    const float* x = (const float*)d_in[0];
    float* out = (float*)d_out;
    unsigned out_elems = (unsigned)out_size;

    unsigned extraElems  = (out_elems > PATCH_ELEMS) ? (out_elems - PATCH_ELEMS) : 0u;
    unsigned extraBlocks = (extraElems + THREADS - 1u) / THREADS;
    Patcher_78280073937146_kernel<<<NROWCTAS + extraBlocks, THREADS>>>(x, out, out_elems);
}

// round 10
// speedup vs baseline: 1.3436x; 1.0965x over previous
#include <cuda_runtime.h>
#include <cuda_bf16.h>
#include <stdint.h>

// x: (B=8, C=3, H=1024, W=1024) fp32; patch=24, stride=16, reflect m=4
// out: (8*64*64, 576, 3) fp32 = 56,623,104 elems (+ maybe (nH,nW)=(64,64)).
#define PATCH_ELEMS 56623104u
#define NROWCTAS 6144u         // 4 image-pairs x 64 ph x 24 iu
#define THREADS  384u          // one thread per (pw, jq) quad of the row
#define B_OFF_IN  (12u << 20)  // +4 images in input floats
#define B_OFF_OUT 7077888u     // +4 images in output float4s (4*4096*432)

__device__ __forceinline__ int reflect1024(int v) {
    v = (v < 0) ? -v : v;                 // jnp 'reflect' (no edge repeat)
    v = (v >= 1024) ? (2046 - v) : v;
    return v;
}

__global__ __launch_bounds__(THREADS, 4)
void Patcher_78280073937146_kernel(const float* __restrict__ x,
                                   float* __restrict__ out,
                                   unsigned out_elems) {
    __shared__ float4 smq[2304];          // 36 KB: staged output, images A|B

    unsigned bid = blockIdx.x;
    unsigned t   = threadIdx.x;

    if (bid >= NROWCTAS) {
        // trailing (nH, nW) = (64, 64) slots, if the harness appends them
        unsigned e = PATCH_ELEMS + (bid - NROWCTAS) * THREADS + t;
        if (e < out_elems) out[e] = 64.0f;
        return;
    }

    // ---- CTA decode: one (b4, ph, iu) row for images b4 and b4+4 ----
    unsigned b4  = bid / 1536u;           // 0..3
    unsigned rem = bid - b4 * 1536u;
    unsigned ph  = rem / 24u;             // 0..63
    unsigned iu  = rem - ph * 24u;        // 0..23

    int y = reflect1024((int)(ph * 16u + iu) - 4);
    unsigned baseA = ((b4 * 3u) << 20) + (((unsigned)y) << 10);
    unsigned baseB = baseA + B_OFF_IN;

    // ---- per-thread: quad (pw, jq), both images, 6 front-batched LDG.128 ----
    unsigned pw = t / 6u;
    unsigned jq = t - pw * 6u;
    int x0 = (int)(pw * 16u + (jq << 2)) - 4;   // -4 .. 1024, 16B-aligned

    float4 a0, a1, a2, c0, c1, c2;
    if ((unsigned)x0 <= 1020u) {
        const float* pa = x + baseA + (unsigned)x0;
        const float* pb = x + baseB + (unsigned)x0;
        a0 = *reinterpret_cast<const float4*>(pa);
        a1 = *reinterpret_cast<const float4*>(pa + (1u << 20));
        a2 = *reinterpret_cast<const float4*>(pa + (2u << 20));
        c0 = *reinterpret_cast<const float4*>(pb);
        c1 = *reinterpret_cast<const float4*>(pb + (1u << 20));
        c2 = *reinterpret_cast<const float4*>(pb + (2u << 20));
    } else {
        // threads 0 (x0=-4) and 383 (x0=1024) only: reflected scalar gather
        float ta[3][4], tb[3][4];
        #pragma unroll
        for (int k = 0; k < 4; ++k) {
            unsigned xr = (unsigned)reflect1024(x0 + k);
            #pragma unroll
            for (int c = 0; c < 3; ++c) {
                ta[c][k] = x[baseA + (((unsigned)c) << 20) + xr];
                tb[c][k] = x[baseB + (((unsigned)c) << 20) + xr];
            }
        }
        a0 = make_float4(ta[0][0], ta[0][1], ta[0][2], ta[0][3]);
        a1 = make_float4(ta[1][0], ta[1][1], ta[1][2], ta[1][3]);
        a2 = make_float4(ta[2][0], ta[2][1], ta[2][2], ta[2][3]);
        c0 = make_float4(tb[0][0], tb[0][1], tb[0][2], tb[0][3]);
        c1 = make_float4(tb[1][0], tb[1][1], tb[1][2], tb[1][3]);
        c2 = make_float4(tb[2][0], tb[2][1], tb[2][2], tb[2][3]);
    }

    // ---- permute channel-major -> (pixel, channel); stage both rows ----
    smq[t * 3u + 0u]    = make_float4(a0.x, a1.x, a2.x, a0.y);
    smq[t * 3u + 1u]    = make_float4(a1.y, a2.y, a0.z, a1.z);
    smq[t * 3u + 2u]    = make_float4(a2.z, a0.w, a1.w, a2.w);
    smq[1152u + t * 3u + 0u] = make_float4(c0.x, c1.x, c2.x, c0.y);
    smq[1152u + t * 3u + 1u] = make_float4(c1.y, c2.y, c0.z, c1.z);
    smq[1152u + t * 3u + 2u] = make_float4(c2.z, c0.w, c1.w, c2.w);
    __syncthreads();

    // ---- emit: per image, 64 patches x 18 float4 (288B contiguous) ----
    unsigned outBase = ((b4 << 12) + (ph << 6)) * 432u + iu * 18u;
    float4* ov = reinterpret_cast<float4*>(out);
    #pragma unroll
    for (unsigned i = 0; i < 3u; ++i) {
        unsigned f   = t + i * THREADS;   // 0..1151
        unsigned pwS = f / 18u;
        unsigned r   = f - pwS * 18u;
        unsigned go  = outBase + pwS * 432u + r;
        __stcs(ov + go,             smq[f]);
        __stcs(ov + go + B_OFF_OUT, smq[1152u + f]);
    }
}

extern "C" void kernel_launch(void* const* d_in, const int* in_sizes, int n_in,
                              void* d_out, int out_size) {
    const float* x = (const float*)d_in[0];
    float* out = (float*)d_out;
    unsigned out_elems = (unsigned)out_size;

    unsigned extraElems  = (out_elems > PATCH_ELEMS) ? (out_elems - PATCH_ELEMS) : 0u;
    unsigned extraBlocks = (extraElems + THREADS - 1u) / THREADS;
    Patcher_78280073937146_kernel<<<NROWCTAS + extraBlocks, THREADS>>>(x, out, out_elems);
}

// round 11
// speedup vs baseline: 1.4012x; 1.0429x over previous
#include <cuda_runtime.h>
#include <cuda_bf16.h>
#include <stdint.h>

// x: (B=8, C=3, H=1024, W=1024) fp32; patch=24, stride=16, reflect m=4
// out: (8*64*64, 576, 3) fp32 = 56,623,104 elems (+ maybe (nH,nW)=(64,64)).
#define PATCH_ELEMS 56623104u
#define NROWCTAS 6144u         // 4 image-pairs x 64 ph x 24 iu
#define THREADS  384u          // one thread per (pw, jq) quad of the row
#define B_OFF_IN  (12u << 20)  // +4 images in input floats
#define B_OFF_OUT 7077888u     // +4 images in output float4s (4*4096*432)

__device__ __forceinline__ int reflect1024(int v) {
    v = (v < 0) ? -v : v;                 // jnp 'reflect' (no edge repeat)
    v = (v >= 1024) ? (2046 - v) : v;
    return v;
}

__global__ __launch_bounds__(THREADS, 4)
void Patcher_78280073937146_kernel(const float* __restrict__ x,
                                   float* __restrict__ out,
                                   unsigned out_elems) {
    __shared__ float4 smq[2304];          // 36 KB: staged output, images A|B

    unsigned bid = blockIdx.x;
    unsigned t   = threadIdx.x;

    if (bid >= NROWCTAS) {
        // trailing (nH, nW) = (64, 64) slots, if the harness appends them
        unsigned e = PATCH_ELEMS + (bid - NROWCTAS) * THREADS + t;
        if (e < out_elems) out[e] = 64.0f;
        return;
    }

    unsigned lane = t & 31u;
    unsigned w    = t >> 5;

    // ---- CTA decode: one (b4, ph, iu) row for images b4 and b4+4 ----
    unsigned b4  = bid / 1536u;           // 0..3
    unsigned rem = bid - b4 * 1536u;
    unsigned ph  = rem / 24u;             // 0..63
    unsigned iu  = rem - ph * 24u;        // 0..23

    int y = reflect1024((int)(ph * 16u + iu) - 4);
    unsigned baseA = ((b4 * 3u) << 20) + (((unsigned)y) << 10);
    unsigned baseB = baseA + B_OFF_IN;

    // ---- per-thread: quad (pw, jq), both images, 6 front-batched LDG.128 ----
    unsigned pw = t / 6u;
    unsigned jq = t - pw * 6u;
    int x0 = (int)(pw * 16u + (jq << 2)) - 4;   // -4 .. 1024, 16B-aligned

    float4 a0, a1, a2, c0, c1, c2;
    if ((unsigned)x0 <= 1020u) {
        const float* pa = x + baseA + (unsigned)x0;
        const float* pb = x + baseB + (unsigned)x0;
        a0 = *reinterpret_cast<const float4*>(pa);
        a1 = *reinterpret_cast<const float4*>(pa + (1u << 20));
        a2 = *reinterpret_cast<const float4*>(pa + (2u << 20));
        c0 = *reinterpret_cast<const float4*>(pb);
        c1 = *reinterpret_cast<const float4*>(pb + (1u << 20));
        c2 = *reinterpret_cast<const float4*>(pb + (2u << 20));
    } else {
        // threads 0 (x0=-4) and 383 (x0=1024) only: reflected scalar gather
        float ta[3][4], tb[3][4];
        #pragma unroll
        for (int k = 0; k < 4; ++k) {
            unsigned xr = (unsigned)reflect1024(x0 + k);
            #pragma unroll
            for (int c = 0; c < 3; ++c) {
                ta[c][k] = x[baseA + (((unsigned)c) << 20) + xr];
                tb[c][k] = x[baseB + (((unsigned)c) << 20) + xr];
            }
        }
        a0 = make_float4(ta[0][0], ta[0][1], ta[0][2], ta[0][3]);
        a1 = make_float4(ta[1][0], ta[1][1], ta[1][2], ta[1][3]);
        a2 = make_float4(ta[2][0], ta[2][1], ta[2][2], ta[2][3]);
        c0 = make_float4(tb[0][0], tb[0][1], tb[0][2], tb[0][3]);
        c1 = make_float4(tb[1][0], tb[1][1], tb[1][2], tb[1][3]);
        c2 = make_float4(tb[2][0], tb[2][1], tb[2][2], tb[2][3]);
    }

    // ---- permute channel-major -> (pixel, channel); stage (warp-local) ----
    smq[t * 3u + 0u]         = make_float4(a0.x, a1.x, a2.x, a0.y);
    smq[t * 3u + 1u]         = make_float4(a1.y, a2.y, a0.z, a1.z);
    smq[t * 3u + 2u]         = make_float4(a2.z, a0.w, a1.w, a2.w);
    smq[1152u + t * 3u + 0u] = make_float4(c0.x, c1.x, c2.x, c0.y);
    smq[1152u + t * 3u + 1u] = make_float4(c1.y, c2.y, c0.z, c1.z);
    smq[1152u + t * 3u + 2u] = make_float4(c2.z, c0.w, c1.w, c2.w);
    __syncwarp();   // exchange is warp-local: slots [96w, 96w+96) written by warp w

    // ---- emit: warp w covers block-level f in [96w, 96w+96) ----
    unsigned outBase = ((b4 << 12) + (ph << 6)) * 432u + iu * 18u;
    float4* ov = reinterpret_cast<float4*>(out);
    unsigned f0 = w * 96u + lane;
    #pragma unroll
    for (unsigned i = 0; i < 3u; ++i) {
        unsigned f   = f0 + i * 32u;      // 0..1151
        unsigned pwS = f / 18u;
        unsigned r   = f - pwS * 18u;
        unsigned go  = outBase + pwS * 432u + r;
        __stcs(ov + go,             smq[f]);
        __stcs(ov + go + B_OFF_OUT, smq[1152u + f]);
    }
}

extern "C" void kernel_launch(void* const* d_in, const int* in_sizes, int n_in,
                              void* d_out, int out_size) {
    const float* x = (const float*)d_in[0];
    float* out = (float*)d_out;
    unsigned out_elems = (unsigned)out_size;

    unsigned extraElems  = (out_elems > PATCH_ELEMS) ? (out_elems - PATCH_ELEMS) : 0u;
    unsigned extraBlocks = (extraElems + THREADS - 1u) / THREADS;
    Patcher_78280073937146_kernel<<<NROWCTAS + extraBlocks, THREADS>>>(x, out, out_elems);
}